// round 1
// baseline (speedup 1.0000x reference)
#include <cuda_runtime.h>

#define NN 50000
#define NE 1000000

// Scratch (allocation-free rule: __device__ globals)
__device__ float g_P[NN * 64];    // x_v @ W_av^T
__device__ float g_S[NN * 64];    // unnormalized weighted message sums
__device__ float g_den[NN];       // sum of exp(e) per dst

// ---------------------------------------------------------------------------
// K0: P = x_v @ W_av^T ; zero S and den.  4 nodes per 256-thread block.
// ---------------------------------------------------------------------------
__global__ void __launch_bounds__(256) node_pre_kernel(
    const float* __restrict__ x_v, const float* __restrict__ W_av)
{
    __shared__ float4 sW[64][17];   // [c][k4], padded: 8-lane LDS.128 phases conflict-free
    __shared__ float4 sx[4][16];
    int tid = threadIdx.x;
    const float4* W4 = (const float4*)W_av;
    for (int i = tid; i < 1024; i += 256) sW[i >> 4][i & 15] = W4[i];
    int base = blockIdx.x * 4;
    if (tid < 64) ((float4*)sx)[tid] = ((const float4*)(x_v + (size_t)base * 64))[tid];
    __syncthreads();

    int nl = tid >> 6, c = tid & 63;
    float acc = 0.f;
#pragma unroll
    for (int k = 0; k < 16; k++) {
        float4 xv = sx[nl][k];
        float4 wv = sW[c][k];
        acc = fmaf(xv.x, wv.x, acc);
        acc = fmaf(xv.y, wv.y, acc);
        acc = fmaf(xv.z, wv.z, acc);
        acc = fmaf(xv.w, wv.w, acc);
    }
    int n = base + nl;
    g_P[n * 64 + c] = acc;
    g_S[n * 64 + c] = 0.f;
    if (c == 0) g_den[n] = 0.f;
}

// ---------------------------------------------------------------------------
// K1: edge kernel. One thread per edge, weights in SMEM (broadcast LDS).
//   e      = x_a . w_att + b_att ;  w = exp(e)
//   den[dst]  += w                        (scalar atomic)
//   S[dst][:] += w * (x_a @ W_va^T)       (red.global.add.v4.f32)
//   out_a[e]   = x_a @ W_aa^T + b_aa + P[src] + P[dst]
// ---------------------------------------------------------------------------
__global__ void __launch_bounds__(256) edge_kernel(
    const float* __restrict__ x_a, const int* __restrict__ arc,
    const float* __restrict__ W_va,
    const float* __restrict__ W_att, const float* __restrict__ b_att,
    const float* __restrict__ W_aa, const float* __restrict__ b_aa,
    float* __restrict__ out_a)
{
    __shared__ float4 sWva[64][16];   // [j][k4] — uniform (broadcast) access per warp
    __shared__ float4 sWaa[64][16];
    __shared__ float4 sAtt[16];
    __shared__ float  sBaa[64];
    __shared__ float  sBatt;

    int tid = threadIdx.x;
    for (int i = tid; i < 1024; i += 256) {
        ((float4*)sWva)[i] = ((const float4*)W_va)[i];
        ((float4*)sWaa)[i] = ((const float4*)W_aa)[i];
    }
    if (tid < 16) sAtt[tid] = ((const float4*)W_att)[tid];
    if (tid < 64) sBaa[tid] = b_aa[tid];
    if (tid == 0) sBatt = b_att[0];
    __syncthreads();

    int e = blockIdx.x * 256 + tid;
    if (e >= NE) return;

    float4 xr[16];
    const float4* xa4 = (const float4*)x_a + (size_t)e * 16;
#pragma unroll
    for (int k = 0; k < 16; k++) xr[k] = xa4[k];

    // attention logit + softmax numerator (max-shift cancels in the ratio)
    float eatt = sBatt;
#pragma unroll
    for (int k = 0; k < 16; k++) {
        float4 wv = sAtt[k];
        eatt = fmaf(xr[k].x, wv.x, eatt);
        eatt = fmaf(xr[k].y, wv.y, eatt);
        eatt = fmaf(xr[k].z, wv.z, eatt);
        eatt = fmaf(xr[k].w, wv.w, eatt);
    }
    float w = __expf(eatt);

    int src = arc[e];
    int dst = arc[NE + e];

    atomicAdd(&g_den[dst], w);

    // weighted message scatter
    float* Sd = g_S + (size_t)dst * 64;
    for (int j0 = 0; j0 < 64; j0 += 4) {
        float a0 = 0.f, a1 = 0.f, a2 = 0.f, a3 = 0.f;
#pragma unroll
        for (int k = 0; k < 16; k++) {
            float4 xv = xr[k];
            float4 w0 = sWva[j0 + 0][k];
            float4 w1 = sWva[j0 + 1][k];
            float4 w2 = sWva[j0 + 2][k];
            float4 w3 = sWva[j0 + 3][k];
            a0 = fmaf(xv.x, w0.x, a0); a0 = fmaf(xv.y, w0.y, a0);
            a0 = fmaf(xv.z, w0.z, a0); a0 = fmaf(xv.w, w0.w, a0);
            a1 = fmaf(xv.x, w1.x, a1); a1 = fmaf(xv.y, w1.y, a1);
            a1 = fmaf(xv.z, w1.z, a1); a1 = fmaf(xv.w, w1.w, a1);
            a2 = fmaf(xv.x, w2.x, a2); a2 = fmaf(xv.y, w2.y, a2);
            a2 = fmaf(xv.z, w2.z, a2); a2 = fmaf(xv.w, w2.w, a2);
            a3 = fmaf(xv.x, w3.x, a3); a3 = fmaf(xv.y, w3.y, a3);
            a3 = fmaf(xv.z, w3.z, a3); a3 = fmaf(xv.w, w3.w, a3);
        }
        asm volatile("red.global.add.v4.f32 [%0], {%1, %2, %3, %4};"
                     :: "l"(Sd + j0),
                        "f"(a0 * w), "f"(a1 * w), "f"(a2 * w), "f"(a3 * w)
                     : "memory");
    }

    // arc update
    const float4* Ps = (const float4*)(g_P + (size_t)src * 64);
    const float4* Pd = (const float4*)(g_P + (size_t)dst * 64);
    float4* Oa = (float4*)out_a + (size_t)e * 16;
    for (int q = 0; q < 16; q++) {
        int j0 = q * 4;
        float a0 = 0.f, a1 = 0.f, a2 = 0.f, a3 = 0.f;
#pragma unroll
        for (int k = 0; k < 16; k++) {
            float4 xv = xr[k];
            float4 w0 = sWaa[j0 + 0][k];
            float4 w1 = sWaa[j0 + 1][k];
            float4 w2 = sWaa[j0 + 2][k];
            float4 w3 = sWaa[j0 + 3][k];
            a0 = fmaf(xv.x, w0.x, a0); a0 = fmaf(xv.y, w0.y, a0);
            a0 = fmaf(xv.z, w0.z, a0); a0 = fmaf(xv.w, w0.w, a0);
            a1 = fmaf(xv.x, w1.x, a1); a1 = fmaf(xv.y, w1.y, a1);
            a1 = fmaf(xv.z, w1.z, a1); a1 = fmaf(xv.w, w1.w, a1);
            a2 = fmaf(xv.x, w2.x, a2); a2 = fmaf(xv.y, w2.y, a2);
            a2 = fmaf(xv.z, w2.z, a2); a2 = fmaf(xv.w, w2.w, a2);
            a3 = fmaf(xv.x, w3.x, a3); a3 = fmaf(xv.y, w3.y, a3);
            a3 = fmaf(xv.z, w3.z, a3); a3 = fmaf(xv.w, w3.w, a3);
        }
        float4 ps = Ps[q], pd = Pd[q];
        float4 o;
        o.x = a0 + sBaa[j0 + 0] + ps.x + pd.x;
        o.y = a1 + sBaa[j0 + 1] + ps.y + pd.y;
        o.z = a2 + sBaa[j0 + 2] + ps.z + pd.z;
        o.w = a3 + sBaa[j0 + 3] + ps.w + pd.w;
        Oa[q] = o;
    }
}

// ---------------------------------------------------------------------------
// K2: h_v = x_v @ W_vv^T + b_vv + S/den  (0 for empty segments)
// ---------------------------------------------------------------------------
__global__ void __launch_bounds__(256) node_post_kernel(
    const float* __restrict__ x_v, const float* __restrict__ W_vv,
    const float* __restrict__ b_vv, float* __restrict__ out_v)
{
    __shared__ float4 sW[64][17];
    __shared__ float4 sx[4][16];
    __shared__ float  sb[64];
    int tid = threadIdx.x;
    const float4* W4 = (const float4*)W_vv;
    for (int i = tid; i < 1024; i += 256) sW[i >> 4][i & 15] = W4[i];
    if (tid < 64) sb[tid] = b_vv[tid];
    int base = blockIdx.x * 4;
    if (tid < 64) ((float4*)sx)[tid] = ((const float4*)(x_v + (size_t)base * 64))[tid];
    __syncthreads();

    int nl = tid >> 6, c = tid & 63;
    float acc = 0.f;
#pragma unroll
    for (int k = 0; k < 16; k++) {
        float4 xv = sx[nl][k];
        float4 wv = sW[c][k];
        acc = fmaf(xv.x, wv.x, acc);
        acc = fmaf(xv.y, wv.y, acc);
        acc = fmaf(xv.z, wv.z, acc);
        acc = fmaf(xv.w, wv.w, acc);
    }
    int n = base + nl;
    float den = g_den[n];
    float s = g_S[n * 64 + c];
    float msg = (den > 0.f) ? (s / den) : 0.f;
    out_v[n * 64 + c] = acc + sb[c] + msg;
}

// ---------------------------------------------------------------------------
extern "C" void kernel_launch(void* const* d_in, const int* in_sizes, int n_in,
                              void* d_out, int out_size)
{
    const float* x_v   = (const float*)d_in[0];
    const float* x_a   = (const float*)d_in[1];
    const int*   arc   = (const int*)  d_in[2];
    const float* W_vv  = (const float*)d_in[3];
    const float* b_vv  = (const float*)d_in[4];
    const float* W_va  = (const float*)d_in[5];
    const float* W_att = (const float*)d_in[6];
    const float* b_att = (const float*)d_in[7];
    const float* W_aa  = (const float*)d_in[8];
    const float* b_aa  = (const float*)d_in[9];
    const float* W_av  = (const float*)d_in[10];

    float* out_v = (float*)d_out;                     // [NN, 64]
    float* out_a = (float*)d_out + (size_t)NN * 64;   // [NE, 64]

    node_pre_kernel<<<NN / 4, 256>>>(x_v, W_av);
    edge_kernel<<<(NE + 255) / 256, 256>>>(x_a, arc, W_va, W_att, b_att,
                                           W_aa, b_aa, out_a);
    node_post_kernel<<<NN / 4, 256>>>(x_v, W_vv, b_vv, out_v);
}